// round 2
// baseline (speedup 1.0000x reference)
#include <cuda_runtime.h>
#include <math.h>

#define BATCH 4
#define CCH   512
#define HCH   64
#define NPIX  4096

// Scratch (device globals — no allocation allowed)
__device__ __align__(16) float g_fgh[3 * BATCH * HCH * NPIX];  // f,g,h projections
__device__ __align__(16) float g_o[BATCH * HCH * NPIX];        // attention output o
__device__ float g_invsig[4];                                  // 1/sigma per weight

// ---------------------------------------------------------------------------
// Spectral norm: sigma = || W @ normalize(W^T u) ||_2  (exact reduction of the
// reference power-iteration step). One block per weight matrix.
// ---------------------------------------------------------------------------
__global__ void spectral_kernel(const float* __restrict__ Wf, const float* __restrict__ Wg,
                                const float* __restrict__ Wh, const float* __restrict__ Wv,
                                const float* __restrict__ uf, const float* __restrict__ ug,
                                const float* __restrict__ uh, const float* __restrict__ uv)
{
    __shared__ float u_s[512];
    __shared__ float v_s[512];
    __shared__ float red[512];
    int w = blockIdx.x;
    const float* W; const float* u; int R, Cc;
    if (w == 0)      { W = Wf; u = uf; R = HCH; Cc = CCH; }
    else if (w == 1) { W = Wg; u = ug; R = HCH; Cc = CCH; }
    else if (w == 2) { W = Wh; u = uh; R = HCH; Cc = CCH; }
    else             { W = Wv; u = uv; R = CCH; Cc = HCH; }
    int t = threadIdx.x;  // 512 threads
    if (t < R) u_s[t] = u[t];
    __syncthreads();
    float v = 0.f;
    if (t < Cc) {
        for (int r = 0; r < R; ++r) v += W[r * Cc + t] * u_s[r];
    }
    red[t] = (t < Cc) ? v * v : 0.f;
    __syncthreads();
    for (int s = 256; s > 0; s >>= 1) {
        if (t < s) red[t] += red[t + s];
        __syncthreads();
    }
    float rn = rsqrtf(fmaxf(red[0], 1e-24f));
    if (t < Cc) v_s[t] = v * rn;
    __syncthreads();
    float tv = 0.f;
    if (t < R) {
        const float* row = W + t * Cc;
        for (int c = 0; c < Cc; ++c) tv += row[c] * v_s[c];
    }
    red[t] = (t < R) ? tv * tv : 0.f;
    __syncthreads();
    for (int s = 256; s > 0; s >>= 1) {
        if (t < s) red[t] += red[t + s];
        __syncthreads();
    }
    if (t == 0) g_invsig[w] = rsqrtf(fmaxf(red[0], 1e-24f));
}

// ---------------------------------------------------------------------------
// Projections f,g,h = (W/sigma) @ x + b.  Tile: [64 rows x 128 pixels], K=16.
// grid (N/128, B, 3), 256 threads, 8x4 register tile per thread.
// ---------------------------------------------------------------------------
__global__ void __launch_bounds__(256) proj_kernel(
    const float* __restrict__ x,
    const float* __restrict__ Wf, const float* __restrict__ Wg, const float* __restrict__ Wh,
    const float* __restrict__ bf, const float* __restrict__ bg, const float* __restrict__ bh)
{
    __shared__ __align__(16) float W_s[16 * 64];
    __shared__ __align__(16) float X_s[16 * 128];
    int nb = blockIdx.x, b = blockIdx.y, w = blockIdx.z;
    const float* W    = (w == 0) ? Wf : ((w == 1) ? Wg : Wh);
    const float* bias = (w == 0) ? bf : ((w == 1) ? bg : bh);
    float invs = g_invsig[w];
    int tid = threadIdx.x;
    int tr = tid >> 5, tc = tid & 31;
    int n0 = nb * 128;
    const float* xb = x + (size_t)b * CCH * NPIX;
    float acc[8][4];
#pragma unroll
    for (int i = 0; i < 8; i++)
#pragma unroll
        for (int j = 0; j < 4; j++) acc[i][j] = 0.f;

    int wrow = tid >> 2, wcg = tid & 3;
    for (int c0 = 0; c0 < CCH; c0 += 16) {
        float4 wv = *(const float4*)&W[wrow * CCH + c0 + wcg * 4];
        W_s[(wcg * 4 + 0) * 64 + wrow] = wv.x;
        W_s[(wcg * 4 + 1) * 64 + wrow] = wv.y;
        W_s[(wcg * 4 + 2) * 64 + wrow] = wv.z;
        W_s[(wcg * 4 + 3) * 64 + wrow] = wv.w;
#pragma unroll
        for (int i = 0; i < 2; ++i) {
            int idx = tid + i * 256;
            int row = idx >> 5, c4 = idx & 31;
            *(float4*)&X_s[row * 128 + c4 * 4] =
                *(const float4*)&xb[(size_t)(c0 + row) * NPIX + n0 + c4 * 4];
        }
        __syncthreads();
#pragma unroll
        for (int kc = 0; kc < 16; ++kc) {
            float4 xa = *(const float4*)&X_s[kc * 128 + tc * 4];
            float4 wa = *(const float4*)&W_s[kc * 64 + tr * 8];
            float4 wb = *(const float4*)&W_s[kc * 64 + tr * 8 + 4];
            float wreg[8] = {wa.x, wa.y, wa.z, wa.w, wb.x, wb.y, wb.z, wb.w};
#pragma unroll
            for (int rr = 0; rr < 8; ++rr) {
                acc[rr][0] += wreg[rr] * xa.x;
                acc[rr][1] += wreg[rr] * xa.y;
                acc[rr][2] += wreg[rr] * xa.z;
                acc[rr][3] += wreg[rr] * xa.w;
            }
        }
        __syncthreads();
    }
    float* outp = g_fgh + (size_t)(w * BATCH + b) * HCH * NPIX;
#pragma unroll
    for (int rr = 0; rr < 8; ++rr) {
        int r = tr * 8 + rr;
        float bb = bias[r];
        float4 o;
        o.x = acc[rr][0] * invs + bb;
        o.y = acc[rr][1] * invs + bb;
        o.z = acc[rr][2] * invs + bb;
        o.w = acc[rr][3] * invs + bb;
        *(float4*)&outp[(size_t)r * NPIX + n0 + tc * 4] = o;
    }
}

// ---------------------------------------------------------------------------
// Flash attention: per block, 64 queries; loop over 64-key tiles with online
// softmax.  S = F^T G, O += P H^T, all fp32 FFMA, 4x4 register tiles.
// grid (N/64, B), 256 threads.
// ---------------------------------------------------------------------------
__global__ void __launch_bounds__(256) attn_kernel()
{
    extern __shared__ float smdyn[];
    float* F_s = smdyn;                  // [64][64]  (k-major)
    float* G_s = smdyn + 64 * 64;        // [64][64]  (k-major)
    float* HT  = smdyn + 2 * 64 * 64;    // [64][68]  ([m][kd], padded)
    float* PT  = HT + 64 * 68;           // [64][68]  ([m][n],  padded)

    int qt = blockIdx.x, b = blockIdx.y;
    int tid = threadIdx.x;
    int tn = tid >> 4, tm = tid & 15;
    const float* fptr = g_fgh + (size_t)(0 * BATCH + b) * HCH * NPIX;
    const float* gptr = g_fgh + (size_t)(1 * BATCH + b) * HCH * NPIX;
    const float* hptr = g_fgh + (size_t)(2 * BATCH + b) * HCH * NPIX;
    int n0 = qt * 64;

#pragma unroll
    for (int i = 0; i < 4; ++i) {
        int idx = tid + i * 256;
        int row = idx >> 4, c4 = idx & 15;
        *(float4*)&F_s[row * 64 + c4 * 4] =
            *(const float4*)&fptr[(size_t)row * NPIX + n0 + c4 * 4];
    }

    float oacc[4][4];
#pragma unroll
    for (int i = 0; i < 4; i++)
#pragma unroll
        for (int j = 0; j < 4; j++) oacc[i][j] = 0.f;
    float mrow[4] = {-1e30f, -1e30f, -1e30f, -1e30f};
    float lrow[4] = {0.f, 0.f, 0.f, 0.f};

    for (int kt = 0; kt < 64; ++kt) {
        int m0 = kt * 64;
        __syncthreads();  // protect G_s/HT/PT from previous iteration readers
#pragma unroll
        for (int i = 0; i < 4; ++i) {
            int idx = tid + i * 256;
            int row = idx >> 4, c4 = idx & 15;
            *(float4*)&G_s[row * 64 + c4 * 4] =
                *(const float4*)&gptr[(size_t)row * NPIX + m0 + c4 * 4];
            float4 hv = *(const float4*)&hptr[(size_t)row * NPIX + m0 + c4 * 4];
            HT[(c4 * 4 + 0) * 68 + row] = hv.x;
            HT[(c4 * 4 + 1) * 68 + row] = hv.y;
            HT[(c4 * 4 + 2) * 68 + row] = hv.z;
            HT[(c4 * 4 + 3) * 68 + row] = hv.w;
        }
        __syncthreads();

        float s[4][4];
#pragma unroll
        for (int i = 0; i < 4; i++)
#pragma unroll
            for (int j = 0; j < 4; j++) s[i][j] = 0.f;
#pragma unroll 8
        for (int k = 0; k < 64; ++k) {
            float4 fa = *(const float4*)&F_s[k * 64 + tn * 4];
            float4 ga = *(const float4*)&G_s[k * 64 + tm * 4];
            float fv[4] = {fa.x, fa.y, fa.z, fa.w};
            float gv[4] = {ga.x, ga.y, ga.z, ga.w};
#pragma unroll
            for (int i = 0; i < 4; i++)
#pragma unroll
                for (int j = 0; j < 4; j++) s[i][j] += fv[i] * gv[j];
        }

        // online softmax (rows split across 16 lanes: same-tn half-warps)
#pragma unroll
        for (int i = 0; i < 4; ++i) {
            float mx = fmaxf(fmaxf(s[i][0], s[i][1]), fmaxf(s[i][2], s[i][3]));
#pragma unroll
            for (int off = 8; off > 0; off >>= 1)
                mx = fmaxf(mx, __shfl_xor_sync(0xffffffffu, mx, off));
            float mnew = fmaxf(mrow[i], mx);
            float corr = __expf(mrow[i] - mnew);
            float p0 = __expf(s[i][0] - mnew);
            float p1 = __expf(s[i][1] - mnew);
            float p2 = __expf(s[i][2] - mnew);
            float p3 = __expf(s[i][3] - mnew);
            float ls = p0 + p1 + p2 + p3;
#pragma unroll
            for (int off = 8; off > 0; off >>= 1)
                ls += __shfl_xor_sync(0xffffffffu, ls, off);
            lrow[i] = lrow[i] * corr + ls;
            mrow[i] = mnew;
            oacc[i][0] *= corr; oacc[i][1] *= corr;
            oacc[i][2] *= corr; oacc[i][3] *= corr;
            PT[(tm * 4 + 0) * 68 + tn * 4 + i] = p0;
            PT[(tm * 4 + 1) * 68 + tn * 4 + i] = p1;
            PT[(tm * 4 + 2) * 68 + tn * 4 + i] = p2;
            PT[(tm * 4 + 3) * 68 + tn * 4 + i] = p3;
        }
        __syncthreads();

#pragma unroll 8
        for (int m = 0; m < 64; ++m) {
            float4 pa = *(const float4*)&PT[m * 68 + tn * 4];
            float4 ha = *(const float4*)&HT[m * 68 + tm * 4];
            float pv[4] = {pa.x, pa.y, pa.z, pa.w};
            float hv[4] = {ha.x, ha.y, ha.z, ha.w};
#pragma unroll
            for (int i = 0; i < 4; i++)
#pragma unroll
                for (int j = 0; j < 4; j++) oacc[i][j] += pv[i] * hv[j];
        }
    }

    float* ob = g_o + (size_t)b * HCH * NPIX;
#pragma unroll
    for (int i = 0; i < 4; ++i) {
        float inv = 1.f / lrow[i];
#pragma unroll
        for (int j = 0; j < 4; ++j) {
            ob[(size_t)(tm * 4 + j) * NPIX + n0 + tn * 4 + i] = oacc[i][j] * inv;
        }
    }
}

// ---------------------------------------------------------------------------
// Output projection + residual: out = gamma*((Wv/sigma) @ o + bv) + x
// grid (N/128, C/64, B), 256 threads, same tiling as proj_kernel.
// ---------------------------------------------------------------------------
__global__ void __launch_bounds__(256) outproj_kernel(
    const float* __restrict__ x, const float* __restrict__ Wv,
    const float* __restrict__ bv, const float* __restrict__ gamma,
    float* __restrict__ out)
{
    __shared__ __align__(16) float W_s[16 * 64];
    __shared__ __align__(16) float O_s[16 * 128];
    int nb = blockIdx.x, ct = blockIdx.y, b = blockIdx.z;
    int tid = threadIdx.x;
    int tr = tid >> 5, tc = tid & 31;
    int n0 = nb * 128, c0 = ct * 64;
    const float* ob = g_o + (size_t)b * HCH * NPIX;
    float invs = g_invsig[3];
    float gm = gamma[0];
    float acc[8][4];
#pragma unroll
    for (int i = 0; i < 8; i++)
#pragma unroll
        for (int j = 0; j < 4; j++) acc[i][j] = 0.f;

    int wrow = tid >> 2, wkg = tid & 3;
    for (int k0 = 0; k0 < HCH; k0 += 16) {
        float4 wv4 = *(const float4*)&Wv[(size_t)(c0 + wrow) * HCH + k0 + wkg * 4];
        W_s[(wkg * 4 + 0) * 64 + wrow] = wv4.x;
        W_s[(wkg * 4 + 1) * 64 + wrow] = wv4.y;
        W_s[(wkg * 4 + 2) * 64 + wrow] = wv4.z;
        W_s[(wkg * 4 + 3) * 64 + wrow] = wv4.w;
#pragma unroll
        for (int i = 0; i < 2; ++i) {
            int idx = tid + i * 256;
            int row = idx >> 5, c4 = idx & 31;
            *(float4*)&O_s[row * 128 + c4 * 4] =
                *(const float4*)&ob[(size_t)(k0 + row) * NPIX + n0 + c4 * 4];
        }
        __syncthreads();
#pragma unroll
        for (int kc = 0; kc < 16; ++kc) {
            float4 xa = *(const float4*)&O_s[kc * 128 + tc * 4];
            float4 wa = *(const float4*)&W_s[kc * 64 + tr * 8];
            float4 wb = *(const float4*)&W_s[kc * 64 + tr * 8 + 4];
            float wreg[8] = {wa.x, wa.y, wa.z, wa.w, wb.x, wb.y, wb.z, wb.w};
#pragma unroll
            for (int rr = 0; rr < 8; ++rr) {
                acc[rr][0] += wreg[rr] * xa.x;
                acc[rr][1] += wreg[rr] * xa.y;
                acc[rr][2] += wreg[rr] * xa.z;
                acc[rr][3] += wreg[rr] * xa.w;
            }
        }
        __syncthreads();
    }
#pragma unroll
    for (int rr = 0; rr < 8; ++rr) {
        int c = c0 + tr * 8 + rr;
        float bb = bv[c];
        size_t base = ((size_t)b * CCH + c) * NPIX + n0 + tc * 4;
        float4 xv = *(const float4*)&x[base];
        float4 o;
        o.x = gm * (acc[rr][0] * invs + bb) + xv.x;
        o.y = gm * (acc[rr][1] * invs + bb) + xv.y;
        o.z = gm * (acc[rr][2] * invs + bb) + xv.z;
        o.w = gm * (acc[rr][3] * invs + bb) + xv.w;
        *(float4*)&out[base] = o;
    }
}

// ---------------------------------------------------------------------------
extern "C" void kernel_launch(void* const* d_in, const int* in_sizes, int n_in,
                              void* d_out, int out_size)
{
    const float* x     = (const float*)d_in[0];
    const float* Wf    = (const float*)d_in[1];
    const float* bf    = (const float*)d_in[2];
    const float* Wg    = (const float*)d_in[3];
    const float* bg    = (const float*)d_in[4];
    const float* Wh    = (const float*)d_in[5];
    const float* bh    = (const float*)d_in[6];
    const float* Wv    = (const float*)d_in[7];
    const float* bv    = (const float*)d_in[8];
    const float* uf    = (const float*)d_in[9];
    const float* ug    = (const float*)d_in[10];
    const float* uh    = (const float*)d_in[11];
    const float* uv    = (const float*)d_in[12];
    const float* gamma = (const float*)d_in[13];
    float* out = (float*)d_out;

    const int smem_attn = (64 * 64 * 2 + 64 * 68 * 2) * (int)sizeof(float);  // 67584 B
    cudaFuncSetAttribute(attn_kernel, cudaFuncAttributeMaxDynamicSharedMemorySize, smem_attn);

    spectral_kernel<<<4, 512>>>(Wf, Wg, Wh, Wv, uf, ug, uh, uv);
    proj_kernel<<<dim3(NPIX / 128, BATCH, 3), 256>>>(x, Wf, Wg, Wh, bf, bg, bh);
    attn_kernel<<<dim3(NPIX / 64, BATCH), 256, smem_attn>>>();
    outproj_kernel<<<dim3(NPIX / 128, CCH / 64, BATCH), 256>>>(x, Wv, bv, gamma, out);
}

// round 4
// speedup vs baseline: 1.3776x; 1.3776x over previous
#include <cuda_runtime.h>
#include <cuda_bf16.h>
#include <cstdint>
#include <math.h>

#define BATCH 4
#define CCH   512
#define HCH   64
#define NPIX  4096
#define LOG2E 1.4426950408889634f

// ---------------- device scratch ----------------
__device__ __align__(16) __nv_bfloat16 g_fT_hi[BATCH * NPIX * HCH];
__device__ __align__(16) __nv_bfloat16 g_fT_lo[BATCH * NPIX * HCH];
__device__ __align__(16) __nv_bfloat16 g_gT_hi[BATCH * NPIX * HCH];
__device__ __align__(16) __nv_bfloat16 g_gT_lo[BATCH * NPIX * HCH];
__device__ __align__(16) __nv_bfloat16 g_h_hi[BATCH * HCH * NPIX];
__device__ __align__(16) __nv_bfloat16 g_h_lo[BATCH * HCH * NPIX];
__device__ __align__(16) float g_o[BATCH * HCH * NPIX];
__device__ float g_invsig[4];

// ---------------- helpers (baseline PTX only, no sm_103a-suffix features) ---
__device__ __forceinline__ uint32_t smem_u32(const void* p) {
    uint32_t a;
    asm("{ .reg .u64 t; cvta.to.shared.u64 t, %1; cvt.u32.u64 %0, t; }" : "=r"(a) : "l"(p));
    return a;
}
__device__ __forceinline__ float ex2(float x) {
    float y; asm("ex2.approx.ftz.f32 %0, %1;" : "=f"(y) : "f"(x)); return y;
}
#define SW128(o) ((o) ^ (((o) >> 3) & 0x70))

__device__ __forceinline__ void cp_async16(uint32_t dst, const void* src) {
    asm volatile("cp.async.cg.shared.global [%0], [%1], 16;" :: "r"(dst), "l"(src) : "memory");
}
#define CP_COMMIT() asm volatile("cp.async.commit_group;" ::: "memory")
#define CP_WAIT(n)  asm volatile("cp.async.wait_group %0;" :: "n"(n) : "memory")

__device__ __forceinline__ void ldsm4(uint32_t* r, uint32_t a) {
    asm volatile("ldmatrix.sync.aligned.m8n8.x4.shared.b16 {%0,%1,%2,%3}, [%4];"
                 : "=r"(r[0]), "=r"(r[1]), "=r"(r[2]), "=r"(r[3]) : "r"(a));
}
__device__ __forceinline__ void mma16816(float* c, const uint32_t* a, const uint32_t* b) {
    asm volatile("mma.sync.aligned.m16n8k16.row.col.f32.bf16.bf16.f32 "
                 "{%0,%1,%2,%3}, {%4,%5,%6,%7}, {%8,%9}, {%0,%1,%2,%3};"
                 : "+f"(c[0]), "+f"(c[1]), "+f"(c[2]), "+f"(c[3])
                 : "r"(a[0]), "r"(a[1]), "r"(a[2]), "r"(a[3]), "r"(b[0]), "r"(b[1]));
}
__device__ __forceinline__ uint32_t pack_bf2(__nv_bfloat16 a, __nv_bfloat16 b) {
    __nv_bfloat162 t = __halves2bfloat162(a, b);
    return *reinterpret_cast<uint32_t*>(&t);
}
// copy rows x 128B tile into SW128-swizzled smem via cp.async
__device__ __forceinline__ void cp_tile(uint32_t sbase, const __nv_bfloat16* src,
                                        size_t rstride, int tid, int rows) {
    int total = rows * 8;
    for (int c = tid; c < total; c += 256) {
        int row = c >> 3, j = c & 7;
        cp_async16(sbase + SW128(row * 128 + j * 16), src + row * rstride + j * 8);
    }
}

// ---------------------------------------------------------------------------
// Spectral norm: sigma = || W @ normalize(W^T u) ||
// ---------------------------------------------------------------------------
__global__ void spectral_kernel(const float* __restrict__ Wf, const float* __restrict__ Wg,
                                const float* __restrict__ Wh, const float* __restrict__ Wv,
                                const float* __restrict__ uf, const float* __restrict__ ug,
                                const float* __restrict__ uh, const float* __restrict__ uv)
{
    __shared__ float u_s[512], v_s[512], red[512];
    int w = blockIdx.x;
    const float* W; const float* u; int R, Cc;
    if (w == 0)      { W = Wf; u = uf; R = HCH; Cc = CCH; }
    else if (w == 1) { W = Wg; u = ug; R = HCH; Cc = CCH; }
    else if (w == 2) { W = Wh; u = uh; R = HCH; Cc = CCH; }
    else             { W = Wv; u = uv; R = CCH; Cc = HCH; }
    int t = threadIdx.x;
    if (t < R) u_s[t] = u[t];
    __syncthreads();
    float v = 0.f;
    if (t < Cc) for (int r = 0; r < R; ++r) v += W[r * Cc + t] * u_s[r];
    red[t] = (t < Cc) ? v * v : 0.f;
    __syncthreads();
    for (int s = 256; s > 0; s >>= 1) { if (t < s) red[t] += red[t + s]; __syncthreads(); }
    float rn = rsqrtf(fmaxf(red[0], 1e-24f));
    if (t < Cc) v_s[t] = v * rn;
    __syncthreads();
    float tv = 0.f;
    if (t < R) { const float* row = W + t * Cc; for (int c = 0; c < Cc; ++c) tv += row[c] * v_s[c]; }
    red[t] = (t < R) ? tv * tv : 0.f;
    __syncthreads();
    for (int s = 256; s > 0; s >>= 1) { if (t < s) red[t] += red[t + s]; __syncthreads(); }
    if (t == 0) g_invsig[w] = rsqrtf(fmaxf(red[0], 1e-24f));
}

// ---------------------------------------------------------------------------
// Projections -> split-bf16 operands.  f,g transposed [n][64]; h natural [64][n].
// f pre-scaled by log2(e) (base-2 softmax).
// ---------------------------------------------------------------------------
__global__ void __launch_bounds__(256) proj_kernel(
    const float* __restrict__ x,
    const float* __restrict__ Wf, const float* __restrict__ Wg, const float* __restrict__ Wh,
    const float* __restrict__ bf, const float* __restrict__ bg, const float* __restrict__ bh)
{
    __shared__ __align__(16) float W_s[16 * 64];
    __shared__ __align__(16) float X_s[16 * 128];
    int nb = blockIdx.x, b = blockIdx.y, w = blockIdx.z;
    const float* W    = (w == 0) ? Wf : ((w == 1) ? Wg : Wh);
    const float* bias = (w == 0) ? bf : ((w == 1) ? bg : bh);
    float invs = g_invsig[w];
    int tid = threadIdx.x;
    int tr = tid >> 5, tc = tid & 31;
    int n0 = nb * 128;
    const float* xb = x + (size_t)b * CCH * NPIX;
    float acc[8][4];
#pragma unroll
    for (int i = 0; i < 8; i++)
#pragma unroll
        for (int j = 0; j < 4; j++) acc[i][j] = 0.f;

    int wrow = tid >> 2, wcg = tid & 3;
    for (int c0 = 0; c0 < CCH; c0 += 16) {
        float4 wv = *(const float4*)&W[wrow * CCH + c0 + wcg * 4];
        W_s[(wcg * 4 + 0) * 64 + wrow] = wv.x;
        W_s[(wcg * 4 + 1) * 64 + wrow] = wv.y;
        W_s[(wcg * 4 + 2) * 64 + wrow] = wv.z;
        W_s[(wcg * 4 + 3) * 64 + wrow] = wv.w;
#pragma unroll
        for (int i = 0; i < 2; ++i) {
            int idx = tid + i * 256;
            int row = idx >> 5, c4 = idx & 31;
            *(float4*)&X_s[row * 128 + c4 * 4] =
                *(const float4*)&xb[(size_t)(c0 + row) * NPIX + n0 + c4 * 4];
        }
        __syncthreads();
#pragma unroll
        for (int kc = 0; kc < 16; ++kc) {
            float4 xa = *(const float4*)&X_s[kc * 128 + tc * 4];
            float4 wa = *(const float4*)&W_s[kc * 64 + tr * 8];
            float4 wb = *(const float4*)&W_s[kc * 64 + tr * 8 + 4];
            float wr[8] = {wa.x, wa.y, wa.z, wa.w, wb.x, wb.y, wb.z, wb.w};
#pragma unroll
            for (int rr = 0; rr < 8; ++rr) {
                acc[rr][0] += wr[rr] * xa.x;
                acc[rr][1] += wr[rr] * xa.y;
                acc[rr][2] += wr[rr] * xa.z;
                acc[rr][3] += wr[rr] * xa.w;
            }
        }
        __syncthreads();
    }

    if (w == 2) {
        __nv_bfloat16* Hh = g_h_hi + (size_t)b * HCH * NPIX;
        __nv_bfloat16* Hl = g_h_lo + (size_t)b * HCH * NPIX;
#pragma unroll
        for (int rr = 0; rr < 8; ++rr) {
            int r = tr * 8 + rr;
            float bb = bias[r];
            uint2 uh, ul;
            __nv_bfloat16 hbv[4], lbv[4];
#pragma unroll
            for (int j = 0; j < 4; ++j) {
                float v = acc[rr][j] * invs + bb;
                hbv[j] = __float2bfloat16_rn(v);
                lbv[j] = __float2bfloat16_rn(v - __bfloat162float(hbv[j]));
            }
            uh.x = pack_bf2(hbv[0], hbv[1]); uh.y = pack_bf2(hbv[2], hbv[3]);
            ul.x = pack_bf2(lbv[0], lbv[1]); ul.y = pack_bf2(lbv[2], lbv[3]);
            *(uint2*)&Hh[(size_t)r * NPIX + n0 + tc * 4] = uh;
            *(uint2*)&Hl[(size_t)r * NPIX + n0 + tc * 4] = ul;
        }
    } else {
        __nv_bfloat16* Th = (w == 0 ? g_fT_hi : g_gT_hi) + (size_t)b * NPIX * HCH;
        __nv_bfloat16* Tl = (w == 0 ? g_fT_lo : g_gT_lo) + (size_t)b * NPIX * HCH;
        float scl = (w == 0) ? LOG2E : 1.0f;
        float bv8[8];
#pragma unroll
        for (int rr = 0; rr < 8; ++rr) bv8[rr] = bias[tr * 8 + rr];
#pragma unroll
        for (int j = 0; j < 4; ++j) {
            int n = n0 + tc * 4 + j;
            uint4 uh, ul;
            __nv_bfloat16 hbv[8], lbv[8];
#pragma unroll
            for (int rr = 0; rr < 8; ++rr) {
                float v = (acc[rr][j] * invs + bv8[rr]) * scl;
                hbv[rr] = __float2bfloat16_rn(v);
                lbv[rr] = __float2bfloat16_rn(v - __bfloat162float(hbv[rr]));
            }
            uh.x = pack_bf2(hbv[0], hbv[1]); uh.y = pack_bf2(hbv[2], hbv[3]);
            uh.z = pack_bf2(hbv[4], hbv[5]); uh.w = pack_bf2(hbv[6], hbv[7]);
            ul.x = pack_bf2(lbv[0], lbv[1]); ul.y = pack_bf2(lbv[2], lbv[3]);
            ul.z = pack_bf2(lbv[4], lbv[5]); ul.w = pack_bf2(lbv[6], lbv[7]);
            *(uint4*)&Th[(size_t)n * HCH + tr * 8] = uh;
            *(uint4*)&Tl[(size_t)n * HCH + tr * 8] = ul;
        }
    }
}

// ---------------------------------------------------------------------------
// mma.sync flash attention.  grid (32, B), 256 threads (8 warps x 16 q-rows).
// SMEM: fT hi/lo 16KB each @0/16384; 2 bufs @32768: each {g_hi,g_lo,h_hi,h_lo} x 8KB
// ---------------------------------------------------------------------------
#define SM_FH 0
#define SM_FL 16384
#define SM_BUF 32768
#define SM_ATTN_TOT 98304

__global__ void __launch_bounds__(256, 1) attn_kernel()
{
    extern __shared__ __align__(128) char smem[];
    int tid = threadIdx.x;
    int lane = tid & 31, wid = tid >> 5;
    int m0 = wid * 16;
    int b = blockIdx.y, n0 = blockIdx.x * 128;
    uint32_t sb = smem_u32(smem);

    size_t bo = (size_t)b * NPIX * HCH;
    const __nv_bfloat16* fTh = g_fT_hi + bo + (size_t)n0 * HCH;
    const __nv_bfloat16* fTl = g_fT_lo + bo + (size_t)n0 * HCH;
    const __nv_bfloat16* gTh = g_gT_hi + bo;
    const __nv_bfloat16* gTl = g_gT_lo + bo;
    const __nv_bfloat16* hh  = g_h_hi + (size_t)b * HCH * NPIX;
    const __nv_bfloat16* hl  = g_h_lo + (size_t)b * HCH * NPIX;

    // prologue: fT + tile0 (group 0), tile1 (group 1)
    cp_tile(sb + SM_FH, fTh, 64, tid, 128);
    cp_tile(sb + SM_FL, fTl, 64, tid, 128);
    {
        uint32_t bb = sb + SM_BUF;
        cp_tile(bb,         gTh, 64, tid, 64);
        cp_tile(bb + 8192,  gTl, 64, tid, 64);
        cp_tile(bb + 16384, hh, NPIX, tid, 64);
        cp_tile(bb + 24576, hl, NPIX, tid, 64);
    }
    CP_COMMIT();
    {
        uint32_t bb = sb + SM_BUF + 32768;
        cp_tile(bb,         gTh + 64 * 64, 64, tid, 64);
        cp_tile(bb + 8192,  gTl + 64 * 64, 64, tid, 64);
        cp_tile(bb + 16384, hh + 64, NPIX, tid, 64);
        cp_tile(bb + 24576, hl + 64, NPIX, tid, 64);
    }
    CP_COMMIT();

    CP_WAIT(1);
    __syncthreads();

    // preload f fragments (A-layout, m16k16 per kc)
    uint32_t fh[4][4], fl[4][4];
    {
        int arow = m0 + (lane & 7) + ((lane >> 3) & 1) * 8;
        int acol = ((lane >> 4) & 1) * 16;
#pragma unroll
        for (int kc = 0; kc < 4; ++kc) {
            uint32_t off = SW128(arow * 128 + kc * 32 + acol);
            ldsm4(fh[kc], sb + SM_FH + off);
            ldsm4(fl[kc], sb + SM_FL + off);
        }
    }

    float oaccv[32];
#pragma unroll
    for (int i = 0; i < 32; ++i) oaccv[i] = 0.f;
    float m0r = -1e30f, m1r = -1e30f, l0 = 0.f, l1 = 0.f;

    // B-frag address offsets (same for g and h tiles)
    int brow = lane & 7;
    int bj = lane >> 3;
    int bcol = (bj & 1) * 16 + (bj >> 1) * 32;

    for (int kt = 0; kt < 64; ++kt) {
        if (kt > 0) { CP_WAIT(1); __syncthreads(); }
        uint32_t gB = sb + SM_BUF + (kt & 1) * 32768;
        uint32_t hB = gB + 16384;

        // ---- S = F G^T (3-term split) ----
        float s[32];
#pragma unroll
        for (int i = 0; i < 32; ++i) s[i] = 0.f;
#pragma unroll
        for (int nt = 0; nt < 8; ++nt) {
            uint32_t bh[8], bl[8];
            uint32_t o0 = SW128((nt * 8 + brow) * 128 + 0 + bcol);
            uint32_t o1 = SW128((nt * 8 + brow) * 128 + 64 + bcol);
            ldsm4(bh,     gB + o0);
            ldsm4(bh + 4, gB + o1);
            ldsm4(bl,     gB + 8192 + o0);
            ldsm4(bl + 4, gB + 8192 + o1);
            float* s4 = &s[nt * 4];
#pragma unroll
            for (int kc = 0; kc < 4; ++kc) {
                mma16816(s4, fh[kc], &bh[kc * 2]);
                mma16816(s4, fh[kc], &bl[kc * 2]);
                mma16816(s4, fl[kc], &bh[kc * 2]);
            }
        }

        // ---- online softmax (base-2); rows r=lane>>2 and r+8, quad-shared ----
        float mx0 = -1e30f, mx1 = -1e30f;
#pragma unroll
        for (int nt = 0; nt < 8; ++nt) {
            mx0 = fmaxf(mx0, fmaxf(s[nt * 4 + 0], s[nt * 4 + 1]));
            mx1 = fmaxf(mx1, fmaxf(s[nt * 4 + 2], s[nt * 4 + 3]));
        }
        mx0 = fmaxf(mx0, __shfl_xor_sync(0xffffffffu, mx0, 1));
        mx0 = fmaxf(mx0, __shfl_xor_sync(0xffffffffu, mx0, 2));
        mx1 = fmaxf(mx1, __shfl_xor_sync(0xffffffffu, mx1, 1));
        mx1 = fmaxf(mx1, __shfl_xor_sync(0xffffffffu, mx1, 2));
        float mn0 = fmaxf(m0r, mx0), mn1 = fmaxf(m1r, mx1);
        float c0 = ex2(m0r - mn0), c1 = ex2(m1r - mn1);
        m0r = mn0; m1r = mn1;
        float ls0 = 0.f, ls1 = 0.f;
#pragma unroll
        for (int nt = 0; nt < 8; ++nt) {
            float p0 = ex2(s[nt * 4 + 0] - mn0);
            float p1 = ex2(s[nt * 4 + 1] - mn0);
            float p2 = ex2(s[nt * 4 + 2] - mn1);
            float p3 = ex2(s[nt * 4 + 3] - mn1);
            s[nt * 4 + 0] = p0; s[nt * 4 + 1] = p1;
            s[nt * 4 + 2] = p2; s[nt * 4 + 3] = p3;
            ls0 += p0 + p1; ls1 += p2 + p3;
        }
        l0 = l0 * c0 + ls0;
        l1 = l1 * c1 + ls1;
#pragma unroll
        for (int nt = 0; nt < 8; ++nt) {
            oaccv[nt * 4 + 0] *= c0; oaccv[nt * 4 + 1] *= c0;
            oaccv[nt * 4 + 2] *= c1; oaccv[nt * 4 + 3] *= c1;
        }

        // ---- P (C-frag) -> A-frag register conversion, hi/lo split ----
        uint32_t ph[4][4], pl[4][4];
#pragma unroll
        for (int j = 0; j < 4; ++j) {
            float* sa = &s[(2 * j) * 4];
            float* sc = &s[(2 * j + 1) * 4];
            __nv_bfloat16 h0 = __float2bfloat16_rn(sa[0]), h1 = __float2bfloat16_rn(sa[1]);
            __nv_bfloat16 h2 = __float2bfloat16_rn(sa[2]), h3 = __float2bfloat16_rn(sa[3]);
            __nv_bfloat16 h4 = __float2bfloat16_rn(sc[0]), h5 = __float2bfloat16_rn(sc[1]);
            __nv_bfloat16 h6 = __float2bfloat16_rn(sc[2]), h7 = __float2bfloat16_rn(sc[3]);
            ph[j][0] = pack_bf2(h0, h1); ph[j][1] = pack_bf2(h2, h3);
            ph[j][2] = pack_bf2(h4, h5); ph[j][3] = pack_bf2(h6, h7);
            pl[j][0] = pack_bf2(__float2bfloat16_rn(sa[0] - __bfloat162float(h0)),
                                __float2bfloat16_rn(sa[1] - __bfloat162float(h1)));
            pl[j][1] = pack_bf2(__float2bfloat16_rn(sa[2] - __bfloat162float(h2)),
                                __float2bfloat16_rn(sa[3] - __bfloat162float(h3)));
            pl[j][2] = pack_bf2(__float2bfloat16_rn(sc[0] - __bfloat162float(h4)),
                                __float2bfloat16_rn(sc[1] - __bfloat162float(h5)));
            pl[j][3] = pack_bf2(__float2bfloat16_rn(sc[2] - __bfloat162float(h6)),
                                __float2bfloat16_rn(sc[3] - __bfloat162float(h7)));
        }

        // ---- O += P H^T (3-term split) ----
#pragma unroll
        for (int nd = 0; nd < 8; ++nd) {
            uint32_t bh[8], bl[8];
            uint32_t o0 = SW128((nd * 8 + brow) * 128 + 0 + bcol);
            uint32_t o1 = SW128((nd * 8 + brow) * 128 + 64 + bcol);
            ldsm4(bh,     hB + o0);
            ldsm4(bh + 4, hB + o1);
            ldsm4(bl,     hB + 8192 + o0);
            ldsm4(bl + 4, hB + 8192 + o1);
            float* o4 = &oaccv[nd * 4];
#pragma unroll
            for (int j = 0; j < 4; ++j) {
                mma16816(o4, ph[j], &bh[j * 2]);
                mma16816(o4, ph[j], &bl[j * 2]);
                mma16816(o4, pl[j], &bh[j * 2]);
            }
        }

        __syncthreads();
        if (kt < 62) {
            uint32_t bb = sb + SM_BUF + (kt & 1) * 32768;
            cp_tile(bb,         gTh + (size_t)(kt + 2) * 64 * 64, 64, tid, 64);
            cp_tile(bb + 8192,  gTl + (size_t)(kt + 2) * 64 * 64, 64, tid, 64);
            cp_tile(bb + 16384, hh + (kt + 2) * 64, NPIX, tid, 64);
            cp_tile(bb + 24576, hl + (kt + 2) * 64, NPIX, tid, 64);
            CP_COMMIT();
        }
    }

    // ---- epilogue: normalize, stage transpose, write o [dim][pix] ----
    l0 += __shfl_xor_sync(0xffffffffu, l0, 1);
    l0 += __shfl_xor_sync(0xffffffffu, l0, 2);
    l1 += __shfl_xor_sync(0xffffffffu, l1, 1);
    l1 += __shfl_xor_sync(0xffffffffu, l1, 2);
    float inv0 = 1.f / l0, inv1 = 1.f / l1;

    float* stage = (float*)(smem + SM_BUF);   // [128][68]
    int q0 = m0 + (lane >> 2), q1 = q0 + 8;
#pragma unroll
    for (int nt = 0; nt < 8; ++nt) {
        int d = nt * 8 + (lane & 3) * 2;
        stage[q0 * 68 + d]     = oaccv[nt * 4 + 0] * inv0;
        stage[q0 * 68 + d + 1] = oaccv[nt * 4 + 1] * inv0;
        stage[q1 * 68 + d]     = oaccv[nt * 4 + 2] * inv1;
        stage[q1 * 68 + d + 1] = oaccv[nt * 4 + 3] * inv1;
    }
    __syncthreads();
    float* ob = g_o + (size_t)b * HCH * NPIX;
    for (int idx = tid; idx < 64 * 128; idx += 256) {
        int d = idx >> 7, q = idx & 127;
        ob[(size_t)d * NPIX + n0 + q] = stage[q * 68 + d];
    }
}

// ---------------------------------------------------------------------------
// out = gamma*((Wv/sigma) @ o + bv) + x
// ---------------------------------------------------------------------------
__global__ void __launch_bounds__(256) outproj_kernel(
    const float* __restrict__ x, const float* __restrict__ Wv,
    const float* __restrict__ bv, const float* __restrict__ gamma,
    float* __restrict__ out)
{
    __shared__ __align__(16) float W_s[16 * 64];
    __shared__ __align__(16) float O_s[16 * 128];
    int nb = blockIdx.x, ct = blockIdx.y, b = blockIdx.z;
    int tid = threadIdx.x;
    int tr = tid >> 5, tc = tid & 31;
    int n0 = nb * 128, c0 = ct * 64;
    const float* ob = g_o + (size_t)b * HCH * NPIX;
    float invs = g_invsig[3];
    float gm = gamma[0];
    float acc[8][4];
#pragma unroll
    for (int i = 0; i < 8; i++)
#pragma unroll
        for (int j = 0; j < 4; j++) acc[i][j] = 0.f;

    int wrow = tid >> 2, wkg = tid & 3;
    for (int k0 = 0; k0 < HCH; k0 += 16) {
        float4 wv4 = *(const float4*)&Wv[(size_t)(c0 + wrow) * HCH + k0 + wkg * 4];
        W_s[(wkg * 4 + 0) * 64 + wrow] = wv4.x;
        W_s[(wkg * 4 + 1) * 64 + wrow] = wv4.y;
        W_s[(wkg * 4 + 2) * 64 + wrow] = wv4.z;
        W_s[(wkg * 4 + 3) * 64 + wrow] = wv4.w;
#pragma unroll
        for (int i = 0; i < 2; ++i) {
            int idx = tid + i * 256;
            int row = idx >> 5, c4 = idx & 31;
            *(float4*)&O_s[row * 128 + c4 * 4] =
                *(const float4*)&ob[(size_t)(k0 + row) * NPIX + n0 + c4 * 4];
        }
        __syncthreads();
#pragma unroll
        for (int kc = 0; kc < 16; ++kc) {
            float4 xa = *(const float4*)&O_s[kc * 128 + tc * 4];
            float4 wa = *(const float4*)&W_s[kc * 64 + tr * 8];
            float4 wb = *(const float4*)&W_s[kc * 64 + tr * 8 + 4];
            float wr[8] = {wa.x, wa.y, wa.z, wa.w, wb.x, wb.y, wb.z, wb.w};
#pragma unroll
            for (int rr = 0; rr < 8; ++rr) {
                acc[rr][0] += wr[rr] * xa.x;
                acc[rr][1] += wr[rr] * xa.y;
                acc[rr][2] += wr[rr] * xa.z;
                acc[rr][3] += wr[rr] * xa.w;
            }
        }
        __syncthreads();
    }
#pragma unroll
    for (int rr = 0; rr < 8; ++rr) {
        int c = c0 + tr * 8 + rr;
        float bb = bv[c];
        size_t base = ((size_t)b * CCH + c) * NPIX + n0 + tc * 4;
        float4 xv = *(const float4*)&x[base];
        float4 o;
        o.x = gm * (acc[rr][0] * invs + bb) + xv.x;
        o.y = gm * (acc[rr][1] * invs + bb) + xv.y;
        o.z = gm * (acc[rr][2] * invs + bb) + xv.z;
        o.w = gm * (acc[rr][3] * invs + bb) + xv.w;
        *(float4*)&out[base] = o;
    }
}

// ---------------------------------------------------------------------------
extern "C" void kernel_launch(void* const* d_in, const int* in_sizes, int n_in,
                              void* d_out, int out_size)
{
    const float* x     = (const float*)d_in[0];
    const float* Wf    = (const float*)d_in[1];
    const float* bf    = (const float*)d_in[2];
    const float* Wg    = (const float*)d_in[3];
    const float* bg    = (const float*)d_in[4];
    const float* Wh    = (const float*)d_in[5];
    const float* bh    = (const float*)d_in[6];
    const float* Wv    = (const float*)d_in[7];
    const float* bv    = (const float*)d_in[8];
    const float* uf    = (const float*)d_in[9];
    const float* ug    = (const float*)d_in[10];
    const float* uh    = (const float*)d_in[11];
    const float* uv    = (const float*)d_in[12];
    const float* gamma = (const float*)d_in[13];
    float* out = (float*)d_out;

    cudaFuncSetAttribute(attn_kernel, cudaFuncAttributeMaxDynamicSharedMemorySize, SM_ATTN_TOT);

    spectral_kernel<<<4, 512>>>(Wf, Wg, Wh, Wv, uf, ug, uh, uv);
    proj_kernel<<<dim3(NPIX / 128, BATCH, 3), 256>>>(x, Wf, Wg, Wh, bf, bg, bh);
    attn_kernel<<<dim3(NPIX / 128, BATCH), 256, SM_ATTN_TOT>>>();
    outproj_kernel<<<dim3(NPIX / 128, CCH / 64, BATCH), 256>>>(x, Wv, bv, gamma, out);
}

// round 5
// speedup vs baseline: 3.3282x; 2.4159x over previous
#include <cuda_runtime.h>
#include <cuda_fp16.h>
#include <cstdint>
#include <math.h>

#define BATCH 4
#define CCH   512
#define HCH   64
#define NPIX  4096
#define LOG2E 1.4426950408889634f

// ---------------- device scratch ----------------
__device__ __align__(16) __half g_fT[BATCH * NPIX * HCH];   // f^T [n][64], pre-scaled log2e
__device__ __align__(16) __half g_gT[BATCH * NPIX * HCH];   // g^T [n][64]
__device__ __align__(16) __half g_h [BATCH * HCH * NPIX];   // h   [64][n]
__device__ __align__(16) float g_o[BATCH * HCH * NPIX];
__device__ float g_invsig[4];

// ---------------- helpers (baseline PTX only) ----------------
__device__ __forceinline__ uint32_t smem_u32(const void* p) {
    uint32_t a;
    asm("{ .reg .u64 t; cvta.to.shared.u64 t, %1; cvt.u32.u64 %0, t; }" : "=r"(a) : "l"(p));
    return a;
}
__device__ __forceinline__ float ex2(float x) {
    float y; asm("ex2.approx.ftz.f32 %0, %1;" : "=f"(y) : "f"(x)); return y;
}
#define SW128(o) ((o) ^ (((o) >> 3) & 0x70))

__device__ __forceinline__ void cp_async16(uint32_t dst, const void* src) {
    asm volatile("cp.async.cg.shared.global [%0], [%1], 16;" :: "r"(dst), "l"(src) : "memory");
}
#define CP_COMMIT() asm volatile("cp.async.commit_group;" ::: "memory")
#define CP_WAIT(n)  asm volatile("cp.async.wait_group %0;" :: "n"(n) : "memory")

__device__ __forceinline__ void ldsm4(uint32_t* r, uint32_t a) {
    asm volatile("ldmatrix.sync.aligned.m8n8.x4.shared.b16 {%0,%1,%2,%3}, [%4];"
                 : "=r"(r[0]), "=r"(r[1]), "=r"(r[2]), "=r"(r[3]) : "r"(a));
}
__device__ __forceinline__ void mma16816(float* c, const uint32_t* a, const uint32_t* b) {
    asm volatile("mma.sync.aligned.m16n8k16.row.col.f32.f16.f16.f32 "
                 "{%0,%1,%2,%3}, {%4,%5,%6,%7}, {%8,%9}, {%0,%1,%2,%3};"
                 : "+f"(c[0]), "+f"(c[1]), "+f"(c[2]), "+f"(c[3])
                 : "r"(a[0]), "r"(a[1]), "r"(a[2]), "r"(a[3]), "r"(b[0]), "r"(b[1]));
}
__device__ __forceinline__ uint32_t pack_h2(__half a, __half b) {
    __half2 t = __halves2half2(a, b);
    return *reinterpret_cast<uint32_t*>(&t);
}
// copy rows x 128B tile into SW128-swizzled smem via cp.async
__device__ __forceinline__ void cp_tile(uint32_t sbase, const __half* src,
                                        size_t rstride, int tid, int rows) {
    int total = rows * 8;
    for (int c = tid; c < total; c += 256) {
        int row = c >> 3, j = c & 7;
        cp_async16(sbase + SW128(row * 128 + j * 16), src + row * rstride + j * 8);
    }
}

// ---------------------------------------------------------------------------
// Spectral norm: sigma = || W @ normalize(W^T u) ||
// ---------------------------------------------------------------------------
__global__ void spectral_kernel(const float* __restrict__ Wf, const float* __restrict__ Wg,
                                const float* __restrict__ Wh, const float* __restrict__ Wv,
                                const float* __restrict__ uf, const float* __restrict__ ug,
                                const float* __restrict__ uh, const float* __restrict__ uv)
{
    __shared__ float u_s[512], v_s[512], red[512];
    int w = blockIdx.x;
    const float* W; const float* u; int R, Cc;
    if (w == 0)      { W = Wf; u = uf; R = HCH; Cc = CCH; }
    else if (w == 1) { W = Wg; u = ug; R = HCH; Cc = CCH; }
    else if (w == 2) { W = Wh; u = uh; R = HCH; Cc = CCH; }
    else             { W = Wv; u = uv; R = CCH; Cc = HCH; }
    int t = threadIdx.x;
    if (t < R) u_s[t] = u[t];
    __syncthreads();
    float v = 0.f;
    if (t < Cc) for (int r = 0; r < R; ++r) v += W[r * Cc + t] * u_s[r];
    red[t] = (t < Cc) ? v * v : 0.f;
    __syncthreads();
    for (int s = 256; s > 0; s >>= 1) { if (t < s) red[t] += red[t + s]; __syncthreads(); }
    float rn = rsqrtf(fmaxf(red[0], 1e-24f));
    if (t < Cc) v_s[t] = v * rn;
    __syncthreads();
    float tv = 0.f;
    if (t < R) { const float* row = W + t * Cc; for (int c = 0; c < Cc; ++c) tv += row[c] * v_s[c]; }
    red[t] = (t < R) ? tv * tv : 0.f;
    __syncthreads();
    for (int s = 256; s > 0; s >>= 1) { if (t < s) red[t] += red[t + s]; __syncthreads(); }
    if (t == 0) g_invsig[w] = rsqrtf(fmaxf(red[0], 1e-24f));
}

// ---------------------------------------------------------------------------
// Projections -> fp16 operands.  f,g transposed [n][64]; h natural [64][n].
// f pre-scaled by log2(e).
// ---------------------------------------------------------------------------
__global__ void __launch_bounds__(256) proj_kernel(
    const float* __restrict__ x,
    const float* __restrict__ Wf, const float* __restrict__ Wg, const float* __restrict__ Wh,
    const float* __restrict__ bf, const float* __restrict__ bg, const float* __restrict__ bh)
{
    __shared__ __align__(16) float W_s[16 * 64];
    __shared__ __align__(16) float X_s[16 * 128];
    int nb = blockIdx.x, b = blockIdx.y, w = blockIdx.z;
    const float* W    = (w == 0) ? Wf : ((w == 1) ? Wg : Wh);
    const float* bias = (w == 0) ? bf : ((w == 1) ? bg : bh);
    float invs = g_invsig[w];
    int tid = threadIdx.x;
    int tr = tid >> 5, tc = tid & 31;
    int n0 = nb * 128;
    const float* xb = x + (size_t)b * CCH * NPIX;
    float acc[8][4];
#pragma unroll
    for (int i = 0; i < 8; i++)
#pragma unroll
        for (int j = 0; j < 4; j++) acc[i][j] = 0.f;

    int wrow = tid >> 2, wcg = tid & 3;
    for (int c0 = 0; c0 < CCH; c0 += 16) {
        float4 wv = *(const float4*)&W[wrow * CCH + c0 + wcg * 4];
        W_s[(wcg * 4 + 0) * 64 + wrow] = wv.x;
        W_s[(wcg * 4 + 1) * 64 + wrow] = wv.y;
        W_s[(wcg * 4 + 2) * 64 + wrow] = wv.z;
        W_s[(wcg * 4 + 3) * 64 + wrow] = wv.w;
#pragma unroll
        for (int i = 0; i < 2; ++i) {
            int idx = tid + i * 256;
            int row = idx >> 5, c4 = idx & 31;
            *(float4*)&X_s[row * 128 + c4 * 4] =
                *(const float4*)&xb[(size_t)(c0 + row) * NPIX + n0 + c4 * 4];
        }
        __syncthreads();
#pragma unroll
        for (int kc = 0; kc < 16; ++kc) {
            float4 xa = *(const float4*)&X_s[kc * 128 + tc * 4];
            float4 wa = *(const float4*)&W_s[kc * 64 + tr * 8];
            float4 wb = *(const float4*)&W_s[kc * 64 + tr * 8 + 4];
            float wr[8] = {wa.x, wa.y, wa.z, wa.w, wb.x, wb.y, wb.z, wb.w};
#pragma unroll
            for (int rr = 0; rr < 8; ++rr) {
                acc[rr][0] += wr[rr] * xa.x;
                acc[rr][1] += wr[rr] * xa.y;
                acc[rr][2] += wr[rr] * xa.z;
                acc[rr][3] += wr[rr] * xa.w;
            }
        }
        __syncthreads();
    }

    if (w == 2) {
        __half* Hp = g_h + (size_t)b * HCH * NPIX;
#pragma unroll
        for (int rr = 0; rr < 8; ++rr) {
            int r = tr * 8 + rr;
            float bb = bias[r];
            __half hv[4];
#pragma unroll
            for (int j = 0; j < 4; ++j) hv[j] = __float2half_rn(acc[rr][j] * invs + bb);
            uint2 u;
            u.x = pack_h2(hv[0], hv[1]); u.y = pack_h2(hv[2], hv[3]);
            *(uint2*)&Hp[(size_t)r * NPIX + n0 + tc * 4] = u;
        }
    } else {
        __half* Tp = (w == 0 ? g_fT : g_gT) + (size_t)b * NPIX * HCH;
        float scl = (w == 0) ? LOG2E : 1.0f;
        float bv8[8];
#pragma unroll
        for (int rr = 0; rr < 8; ++rr) bv8[rr] = bias[tr * 8 + rr];
#pragma unroll
        for (int j = 0; j < 4; ++j) {
            int n = n0 + tc * 4 + j;
            __half hv[8];
#pragma unroll
            for (int rr = 0; rr < 8; ++rr)
                hv[rr] = __float2half_rn((acc[rr][j] * invs + bv8[rr]) * scl);
            uint4 u;
            u.x = pack_h2(hv[0], hv[1]); u.y = pack_h2(hv[2], hv[3]);
            u.z = pack_h2(hv[4], hv[5]); u.w = pack_h2(hv[6], hv[7]);
            *(uint4*)&Tp[(size_t)n * HCH + tr * 8] = u;
        }
    }
}

// ---------------------------------------------------------------------------
// mma.sync (fp16) flash attention.  grid (32, B), 256 threads (8 warps x 16 q).
// SMEM: fT 16KB @0; 2 bufs @16384: {g 8KB, h 8KB} each; epilogue stage @16384.
// ---------------------------------------------------------------------------
#define SM_FH 0
#define SM_BUF 16384
#define SM_ATTN_TOT 51200

__global__ void __launch_bounds__(256, 1) attn_kernel()
{
    extern __shared__ __align__(128) char smem[];
    int tid = threadIdx.x;
    int lane = tid & 31, wid = tid >> 5;
    int m0 = wid * 16;
    int b = blockIdx.y, n0 = blockIdx.x * 128;
    uint32_t sb = smem_u32(smem);

    size_t bo = (size_t)b * NPIX * HCH;
    const __half* fT = g_fT + bo + (size_t)n0 * HCH;
    const __half* gT = g_gT + bo;
    const __half* hp = g_h + (size_t)b * HCH * NPIX;

    cp_tile(sb + SM_FH, fT, 64, tid, 128);
    cp_tile(sb + SM_BUF,        gT, 64, tid, 64);
    cp_tile(sb + SM_BUF + 8192, hp, NPIX, tid, 64);
    CP_COMMIT();
    cp_tile(sb + SM_BUF + 16384, gT + 64 * 64, 64, tid, 64);
    cp_tile(sb + SM_BUF + 24576, hp + 64, NPIX, tid, 64);
    CP_COMMIT();

    CP_WAIT(1);
    __syncthreads();

    // preload f fragments (A-layout m16k16 per kc)
    uint32_t fa[4][4];
    {
        int arow = m0 + (lane & 7) + ((lane >> 3) & 1) * 8;
        int acol = ((lane >> 4) & 1) * 16;
#pragma unroll
        for (int kc = 0; kc < 4; ++kc)
            ldsm4(fa[kc], sb + SM_FH + SW128(arow * 128 + kc * 32 + acol));
    }

    float oaccv[32];
#pragma unroll
    for (int i = 0; i < 32; ++i) oaccv[i] = 0.f;
    float m0r = -1e30f, m1r = -1e30f, l0 = 0.f, l1 = 0.f;

    int brow = lane & 7;
    int bj = lane >> 3;
    int bcol = (bj & 1) * 16 + (bj >> 1) * 32;

    for (int kt = 0; kt < 64; ++kt) {
        if (kt > 0) { CP_WAIT(1); __syncthreads(); }
        uint32_t gB = sb + SM_BUF + (kt & 1) * 16384;
        uint32_t hB = gB + 8192;

        // ---- S = F G^T ----
        float s[32];
#pragma unroll
        for (int i = 0; i < 32; ++i) s[i] = 0.f;
#pragma unroll
        for (int nt = 0; nt < 8; ++nt) {
            uint32_t bfr[8];
            uint32_t o0 = SW128((nt * 8 + brow) * 128 + 0 + bcol);
            uint32_t o1 = SW128((nt * 8 + brow) * 128 + 64 + bcol);
            ldsm4(bfr,     gB + o0);
            ldsm4(bfr + 4, gB + o1);
            float* s4 = &s[nt * 4];
#pragma unroll
            for (int kc = 0; kc < 4; ++kc) mma16816(s4, fa[kc], &bfr[kc * 2]);
        }

        // ---- online softmax (base-2); rows lane>>2 and +8, quad-shared ----
        float mx0 = -1e30f, mx1 = -1e30f;
#pragma unroll
        for (int nt = 0; nt < 8; ++nt) {
            mx0 = fmaxf(mx0, fmaxf(s[nt * 4 + 0], s[nt * 4 + 1]));
            mx1 = fmaxf(mx1, fmaxf(s[nt * 4 + 2], s[nt * 4 + 3]));
        }
        mx0 = fmaxf(mx0, __shfl_xor_sync(0xffffffffu, mx0, 1));
        mx0 = fmaxf(mx0, __shfl_xor_sync(0xffffffffu, mx0, 2));
        mx1 = fmaxf(mx1, __shfl_xor_sync(0xffffffffu, mx1, 1));
        mx1 = fmaxf(mx1, __shfl_xor_sync(0xffffffffu, mx1, 2));
        float mn0 = fmaxf(m0r, mx0), mn1 = fmaxf(m1r, mx1);
        float c0 = ex2(m0r - mn0), c1 = ex2(m1r - mn1);
        m0r = mn0; m1r = mn1;
        float ls0 = 0.f, ls1 = 0.f;
#pragma unroll
        for (int nt = 0; nt < 8; ++nt) {
            float p0 = ex2(s[nt * 4 + 0] - mn0);
            float p1 = ex2(s[nt * 4 + 1] - mn0);
            float p2 = ex2(s[nt * 4 + 2] - mn1);
            float p3 = ex2(s[nt * 4 + 3] - mn1);
            s[nt * 4 + 0] = p0; s[nt * 4 + 1] = p1;
            s[nt * 4 + 2] = p2; s[nt * 4 + 3] = p3;
            ls0 += p0 + p1; ls1 += p2 + p3;
        }
        l0 = l0 * c0 + ls0;
        l1 = l1 * c1 + ls1;
#pragma unroll
        for (int nt = 0; nt < 8; ++nt) {
            oaccv[nt * 4 + 0] *= c0; oaccv[nt * 4 + 1] *= c0;
            oaccv[nt * 4 + 2] *= c1; oaccv[nt * 4 + 3] *= c1;
        }

        // ---- P (C-frag) -> A-frag fp16 ----
        uint32_t pa[4][4];
#pragma unroll
        for (int j = 0; j < 4; ++j) {
            float* sa = &s[(2 * j) * 4];
            float* sc = &s[(2 * j + 1) * 4];
            pa[j][0] = pack_h2(__float2half_rn(sa[0]), __float2half_rn(sa[1]));
            pa[j][1] = pack_h2(__float2half_rn(sa[2]), __float2half_rn(sa[3]));
            pa[j][2] = pack_h2(__float2half_rn(sc[0]), __float2half_rn(sc[1]));
            pa[j][3] = pack_h2(__float2half_rn(sc[2]), __float2half_rn(sc[3]));
        }

        // ---- O += P H^T ----
#pragma unroll
        for (int nd = 0; nd < 8; ++nd) {
            uint32_t bfr[8];
            uint32_t o0 = SW128((nd * 8 + brow) * 128 + 0 + bcol);
            uint32_t o1 = SW128((nd * 8 + brow) * 128 + 64 + bcol);
            ldsm4(bfr,     hB + o0);
            ldsm4(bfr + 4, hB + o1);
            float* o4 = &oaccv[nd * 4];
#pragma unroll
            for (int j = 0; j < 4; ++j) mma16816(o4, pa[j], &bfr[j * 2]);
        }

        __syncthreads();
        if (kt < 62) {
            uint32_t bb = sb + SM_BUF + (kt & 1) * 16384;
            cp_tile(bb,        gT + (size_t)(kt + 2) * 64 * 64, 64, tid, 64);
            cp_tile(bb + 8192, hp + (kt + 2) * 64, NPIX, tid, 64);
            CP_COMMIT();
        }
    }

    // ---- epilogue ----
    l0 += __shfl_xor_sync(0xffffffffu, l0, 1);
    l0 += __shfl_xor_sync(0xffffffffu, l0, 2);
    l1 += __shfl_xor_sync(0xffffffffu, l1, 1);
    l1 += __shfl_xor_sync(0xffffffffu, l1, 2);
    float inv0 = 1.f / l0, inv1 = 1.f / l1;

    float* stage = (float*)(smem + SM_BUF);   // [128][68]
    int q0 = m0 + (lane >> 2), q1 = q0 + 8;
#pragma unroll
    for (int nt = 0; nt < 8; ++nt) {
        int d = nt * 8 + (lane & 3) * 2;
        stage[q0 * 68 + d]     = oaccv[nt * 4 + 0] * inv0;
        stage[q0 * 68 + d + 1] = oaccv[nt * 4 + 1] * inv0;
        stage[q1 * 68 + d]     = oaccv[nt * 4 + 2] * inv1;
        stage[q1 * 68 + d + 1] = oaccv[nt * 4 + 3] * inv1;
    }
    __syncthreads();
    float* ob = g_o + (size_t)b * HCH * NPIX;
    for (int idx = tid; idx < 64 * 128; idx += 256) {
        int d = idx >> 7, q = idx & 127;
        ob[(size_t)d * NPIX + n0 + q] = stage[q * 68 + d];
    }
}

// ---------------------------------------------------------------------------
// out = gamma*((Wv/sigma) @ o + bv) + x
// ---------------------------------------------------------------------------
__global__ void __launch_bounds__(256) outproj_kernel(
    const float* __restrict__ x, const float* __restrict__ Wv,
    const float* __restrict__ bv, const float* __restrict__ gamma,
    float* __restrict__ out)
{
    __shared__ __align__(16) float W_s[16 * 64];
    __shared__ __align__(16) float O_s[16 * 128];
    int nb = blockIdx.x, ct = blockIdx.y, b = blockIdx.z;
    int tid = threadIdx.x;
    int tr = tid >> 5, tc = tid & 31;
    int n0 = nb * 128, c0 = ct * 64;
    const float* ob = g_o + (size_t)b * HCH * NPIX;
    float invs = g_invsig[3];
    float gm = gamma[0];
    float acc[8][4];
#pragma unroll
    for (int i = 0; i < 8; i++)
#pragma unroll
        for (int j = 0; j < 4; j++) acc[i][j] = 0.f;

    int wrow = tid >> 2, wkg = tid & 3;
    for (int k0 = 0; k0 < HCH; k0 += 16) {
        float4 wv4 = *(const float4*)&Wv[(size_t)(c0 + wrow) * HCH + k0 + wkg * 4];
        W_s[(wkg * 4 + 0) * 64 + wrow] = wv4.x;
        W_s[(wkg * 4 + 1) * 64 + wrow] = wv4.y;
        W_s[(wkg * 4 + 2) * 64 + wrow] = wv4.z;
        W_s[(wkg * 4 + 3) * 64 + wrow] = wv4.w;
#pragma unroll
        for (int i = 0; i < 2; ++i) {
            int idx = tid + i * 256;
            int row = idx >> 5, c4 = idx & 31;
            *(float4*)&O_s[row * 128 + c4 * 4] =
                *(const float4*)&ob[(size_t)(k0 + row) * NPIX + n0 + c4 * 4];
        }
        __syncthreads();
#pragma unroll
        for (int kc = 0; kc < 16; ++kc) {
            float4 xa = *(const float4*)&O_s[kc * 128 + tc * 4];
            float4 wa = *(const float4*)&W_s[kc * 64 + tr * 8];
            float4 wb = *(const float4*)&W_s[kc * 64 + tr * 8 + 4];
            float wr[8] = {wa.x, wa.y, wa.z, wa.w, wb.x, wb.y, wb.z, wb.w};
#pragma unroll
            for (int rr = 0; rr < 8; ++rr) {
                acc[rr][0] += wr[rr] * xa.x;
                acc[rr][1] += wr[rr] * xa.y;
                acc[rr][2] += wr[rr] * xa.z;
                acc[rr][3] += wr[rr] * xa.w;
            }
        }
        __syncthreads();
    }
#pragma unroll
    for (int rr = 0; rr < 8; ++rr) {
        int c = c0 + tr * 8 + rr;
        float bb = bv[c];
        size_t base = ((size_t)b * CCH + c) * NPIX + n0 + tc * 4;
        float4 xv = *(const float4*)&x[base];
        float4 o;
        o.x = gm * (acc[rr][0] * invs + bb) + xv.x;
        o.y = gm * (acc[rr][1] * invs + bb) + xv.y;
        o.z = gm * (acc[rr][2] * invs + bb) + xv.z;
        o.w = gm * (acc[rr][3] * invs + bb) + xv.w;
        *(float4*)&out[base] = o;
    }
}

// ---------------------------------------------------------------------------
extern "C" void kernel_launch(void* const* d_in, const int* in_sizes, int n_in,
                              void* d_out, int out_size)
{
    const float* x     = (const float*)d_in[0];
    const float* Wf    = (const float*)d_in[1];
    const float* bf    = (const float*)d_in[2];
    const float* Wg    = (const float*)d_in[3];
    const float* bg    = (const float*)d_in[4];
    const float* Wh    = (const float*)d_in[5];
    const float* bh    = (const float*)d_in[6];
    const float* Wv    = (const float*)d_in[7];
    const float* bv    = (const float*)d_in[8];
    const float* uf    = (const float*)d_in[9];
    const float* ug    = (const float*)d_in[10];
    const float* uh    = (const float*)d_in[11];
    const float* uv    = (const float*)d_in[12];
    const float* gamma = (const float*)d_in[13];
    float* out = (float*)d_out;

    cudaFuncSetAttribute(attn_kernel, cudaFuncAttributeMaxDynamicSharedMemorySize, SM_ATTN_TOT);

    spectral_kernel<<<4, 512>>>(Wf, Wg, Wh, Wv, uf, ug, uh, uv);
    proj_kernel<<<dim3(NPIX / 128, BATCH, 3), 256>>>(x, Wf, Wg, Wh, bf, bg, bh);
    attn_kernel<<<dim3(NPIX / 128, BATCH), 256, SM_ATTN_TOT>>>();
    outproj_kernel<<<dim3(NPIX / 128, CCH / 64, BATCH), 256>>>(x, Wv, bv, gamma, out);
}

// round 6
// speedup vs baseline: 4.9637x; 1.4914x over previous
#include <cuda_runtime.h>
#include <cuda_fp16.h>
#include <cstdint>
#include <math.h>

#define BATCH 4
#define CCH   512
#define HCH   64
#define NPIX  4096
#define LOG2E 1.4426950408889634f

// ---------------- device scratch ----------------
__device__ __align__(16) __half g_fT[BATCH * NPIX * HCH];   // f^T [n][64], pre-scaled log2e
__device__ __align__(16) __half g_gT[BATCH * NPIX * HCH];   // g^T [n][64]
__device__ __align__(16) __half g_h [BATCH * HCH * NPIX];   // h   [64][n]
__device__ __align__(16) __half g_oT[BATCH * NPIX * HCH];   // o^T [n][64]
__device__ __align__(16) __half g_Wp[3 * HCH * CCH];        // W' fp16 (invsig, log2e folded)
__device__ __align__(16) __half g_Wvp[CCH * HCH];           // Wv' fp16 (invsig folded)
__device__ float g_invsig[4];

// ---------------- helpers (baseline PTX only) ----------------
__device__ __forceinline__ uint32_t smem_u32(const void* p) {
    uint32_t a;
    asm("{ .reg .u64 t; cvta.to.shared.u64 t, %1; cvt.u32.u64 %0, t; }" : "=r"(a) : "l"(p));
    return a;
}
__device__ __forceinline__ float ex2(float x) {
    float y; asm("ex2.approx.ftz.f32 %0, %1;" : "=f"(y) : "f"(x)); return y;
}
#define SW128(o) ((o) ^ (((o) >> 3) & 0x70))

__device__ __forceinline__ void cp_async16(uint32_t dst, const void* src) {
    asm volatile("cp.async.cg.shared.global [%0], [%1], 16;" :: "r"(dst), "l"(src) : "memory");
}
#define CP_COMMIT() asm volatile("cp.async.commit_group;" ::: "memory")
#define CP_WAIT(n)  asm volatile("cp.async.wait_group %0;" :: "n"(n) : "memory")

__device__ __forceinline__ void ldsm4(uint32_t* r, uint32_t a) {
    asm volatile("ldmatrix.sync.aligned.m8n8.x4.shared.b16 {%0,%1,%2,%3}, [%4];"
                 : "=r"(r[0]), "=r"(r[1]), "=r"(r[2]), "=r"(r[3]) : "r"(a));
}
__device__ __forceinline__ void mma16816(float* c, const uint32_t* a, const uint32_t* b) {
    asm volatile("mma.sync.aligned.m16n8k16.row.col.f32.f16.f16.f32 "
                 "{%0,%1,%2,%3}, {%4,%5,%6,%7}, {%8,%9}, {%0,%1,%2,%3};"
                 : "+f"(c[0]), "+f"(c[1]), "+f"(c[2]), "+f"(c[3])
                 : "r"(a[0]), "r"(a[1]), "r"(a[2]), "r"(a[3]), "r"(b[0]), "r"(b[1]));
}
__device__ __forceinline__ uint32_t pack_h2(__half a, __half b) {
    __half2 t = __halves2half2(a, b);
    return *reinterpret_cast<uint32_t*>(&t);
}
// copy rows x 128B tile (half source) into SW128-swizzled smem, 256 threads
__device__ __forceinline__ void cp_tile(uint32_t sbase, const __half* src,
                                        size_t rstride, int tid, int rows) {
    int total = rows * 8;
    for (int c = tid; c < total; c += 256) {
        int row = c >> 3, j = c & 7;
        cp_async16(sbase + SW128(row * 128 + j * 16), src + row * rstride + j * 8);
    }
}

// ---------------------------------------------------------------------------
// Spectral norm: sigma = || W @ normalize(W^T u) ||
// ---------------------------------------------------------------------------
__global__ void spectral_kernel(const float* __restrict__ Wf, const float* __restrict__ Wg,
                                const float* __restrict__ Wh, const float* __restrict__ Wv,
                                const float* __restrict__ uf, const float* __restrict__ ug,
                                const float* __restrict__ uh, const float* __restrict__ uv)
{
    __shared__ float u_s[512], v_s[512], red[512];
    int w = blockIdx.x;
    const float* W; const float* u; int R, Cc;
    if (w == 0)      { W = Wf; u = uf; R = HCH; Cc = CCH; }
    else if (w == 1) { W = Wg; u = ug; R = HCH; Cc = CCH; }
    else if (w == 2) { W = Wh; u = uh; R = HCH; Cc = CCH; }
    else             { W = Wv; u = uv; R = CCH; Cc = HCH; }
    int t = threadIdx.x;
    if (t < R) u_s[t] = u[t];
    __syncthreads();
    float v = 0.f;
    if (t < Cc) for (int r = 0; r < R; ++r) v += W[r * Cc + t] * u_s[r];
    red[t] = (t < Cc) ? v * v : 0.f;
    __syncthreads();
    for (int s = 256; s > 0; s >>= 1) { if (t < s) red[t] += red[t + s]; __syncthreads(); }
    float rn = rsqrtf(fmaxf(red[0], 1e-24f));
    if (t < Cc) v_s[t] = v * rn;
    __syncthreads();
    float tv = 0.f;
    if (t < R) { const float* row = W + t * Cc; for (int c = 0; c < Cc; ++c) tv += row[c] * v_s[c]; }
    red[t] = (t < R) ? tv * tv : 0.f;
    __syncthreads();
    for (int s = 256; s > 0; s >>= 1) { if (t < s) red[t] += red[t + s]; __syncthreads(); }
    if (t == 0) g_invsig[w] = rsqrtf(fmaxf(red[0], 1e-24f));
}

// ---------------------------------------------------------------------------
// Weight conversion: fold invsig (and log2e for Wf) into fp16 weights.
// ---------------------------------------------------------------------------
__global__ void wconv_kernel(const float* __restrict__ Wf, const float* __restrict__ Wg,
                             const float* __restrict__ Wh, const float* __restrict__ Wv)
{
    int idx = blockIdx.x * 256 + threadIdx.x;
    int stride = gridDim.x * 256;
    for (int i = idx; i < 3 * HCH * CCH + CCH * HCH; i += stride) {
        if (i < 3 * HCH * CCH) {
            int w = i / (HCH * CCH), r = i % (HCH * CCH);
            const float* W = (w == 0) ? Wf : ((w == 1) ? Wg : Wh);
            float scl = g_invsig[w] * (w == 0 ? LOG2E : 1.0f);
            g_Wp[i] = __float2half_rn(W[r] * scl);
        } else {
            int r = i - 3 * HCH * CCH;
            g_Wvp[r] = __float2half_rn(Wv[r] * g_invsig[3]);
        }
    }
}

// ---------------------------------------------------------------------------
// Fused MMA projections: one CTA = [128 pix] x one batch; computes f,g,h.
// fT/gT written [pix][64]; h written [64][pix].  grid (32, 4), 256 threads.
// ---------------------------------------------------------------------------
#define PX_XRAW 0
#define PX_XT   65536
#define PX_W    81920
#define PX_BIAS 155648
#define SM_PROJ_TOT 156416

__device__ __forceinline__ void cp_xraw(uint32_t sb, int buf, const float* xb,
                                        int c, int n0, int tid) {
    for (int idx = tid; idx < 64 * 32; idx += 256) {
        int row = idx >> 5, jj = idx & 31;
        cp_async16(sb + PX_XRAW + buf * 32768 + row * 512 + ((jj ^ (row & 7)) << 4),
                   xb + (size_t)(c * 64 + row) * NPIX + n0 + jj * 4);
    }
}
__device__ __forceinline__ void cp_Wchunk(uint32_t sb, int buf, int c, int tid) {
#pragma unroll
    for (int w = 0; w < 3; ++w)
        cp_tile(sb + PX_W + buf * 24576 + w * 8192, g_Wp + w * 32768 + c * 64, 512, tid, 64);
}

__global__ void __launch_bounds__(256, 1) proj_kernel(
    const float* __restrict__ x,
    const float* __restrict__ bf, const float* __restrict__ bg, const float* __restrict__ bh)
{
    extern __shared__ __align__(128) char smem[];
    int tid = threadIdx.x;
    int lane = tid & 31, wid = tid >> 5;
    int wpix0 = wid * 16;
    int nb = blockIdx.x, b = blockIdx.y;
    int n0 = nb * 128;
    uint32_t sb = smem_u32(smem);
    const float* xb = x + (size_t)b * CCH * NPIX;

    // preload chunks 0,1
    cp_xraw(sb, 0, xb, 0, n0, tid); cp_Wchunk(sb, 0, 0, tid); CP_COMMIT();
    cp_xraw(sb, 1, xb, 1, n0, tid); cp_Wchunk(sb, 1, 1, tid); CP_COMMIT();

    // biases
    float* bias_s = (float*)(smem + PX_BIAS);
    if (tid < 192) {
        int w = tid >> 6, d = tid & 63;
        bias_s[tid] = (w == 0) ? bf[d] * LOG2E : ((w == 1) ? bg[d] : bh[d]);
    }

    float cf[8][4], cg[8][4], chh[4][2][4];
#pragma unroll
    for (int i = 0; i < 8; ++i)
#pragma unroll
        for (int j = 0; j < 4; ++j) { cf[i][j] = 0.f; cg[i][j] = 0.f; }
#pragma unroll
    for (int i = 0; i < 4; ++i)
#pragma unroll
        for (int n = 0; n < 2; ++n)
#pragma unroll
            for (int j = 0; j < 4; ++j) chh[i][n][j] = 0.f;

    int brow = lane & 7;
    int bj = lane >> 3;
    int bcol = (bj & 1) * 16 + (bj >> 1) * 32;
    int acolb = ((lane >> 4) & 1) * 16;

    for (int c = 0; c < 8; ++c) {
        CP_WAIT(1);
        __syncthreads();
        // convert xraw[c&1] -> xT [pix][64] fp16 swizzled
        {
            int ch = tid & 63, q4 = tid >> 6;
            const char* xr = smem + PX_XRAW + (c & 1) * 32768 + ch * 512;
#pragma unroll
            for (int i = 0; i < 8; ++i) {
                int j = q4 * 8 + i;
                float4 v = *(const float4*)(xr + ((j ^ (ch & 7)) << 4));
                int p = j * 4;
                *(__half*)(smem + PX_XT + SW128((p + 0) * 128 + ch * 2)) = __float2half_rn(v.x);
                *(__half*)(smem + PX_XT + SW128((p + 1) * 128 + ch * 2)) = __float2half_rn(v.y);
                *(__half*)(smem + PX_XT + SW128((p + 2) * 128 + ch * 2)) = __float2half_rn(v.z);
                *(__half*)(smem + PX_XT + SW128((p + 3) * 128 + ch * 2)) = __float2half_rn(v.w);
            }
        }
        __syncthreads();
        if (c < 6) {
            cp_xraw(sb, c & 1, xb, c + 2, n0, tid);
            cp_Wchunk(sb, (c + 2) % 3, c + 2, tid);
            CP_COMMIT();
        }
        // MMA
        uint32_t xtb = sb + PX_XT;
        uint32_t wtb = sb + PX_W + (c % 3) * 24576;
        uint32_t ax[4][4];
        int arow = wpix0 + (lane & 7) + ((lane >> 3) & 1) * 8;
#pragma unroll
        for (int kc = 0; kc < 4; ++kc)
            ldsm4(ax[kc], xtb + SW128(arow * 128 + kc * 32 + acolb));
        // f
#pragma unroll
        for (int nt = 0; nt < 8; ++nt) {
            uint32_t bw[8];
            uint32_t o0 = SW128((nt * 8 + brow) * 128 + bcol);
            uint32_t o1 = SW128((nt * 8 + brow) * 128 + 64 + bcol);
            ldsm4(bw, wtb + o0); ldsm4(bw + 4, wtb + o1);
#pragma unroll
            for (int kc = 0; kc < 4; ++kc) mma16816(cf[nt], ax[kc], &bw[kc * 2]);
        }
        // g
#pragma unroll
        for (int nt = 0; nt < 8; ++nt) {
            uint32_t bw[8];
            uint32_t o0 = SW128((nt * 8 + brow) * 128 + bcol);
            uint32_t o1 = SW128((nt * 8 + brow) * 128 + 64 + bcol);
            ldsm4(bw, wtb + 8192 + o0); ldsm4(bw + 4, wtb + 8192 + o1);
#pragma unroll
            for (int kc = 0; kc < 4; ++kc) mma16816(cg[nt], ax[kc], &bw[kc * 2]);
        }
        // h
        uint32_t bx[2][8];
#pragma unroll
        for (int nt = 0; nt < 2; ++nt) {
            uint32_t o0 = SW128((wpix0 + nt * 8 + brow) * 128 + bcol);
            uint32_t o1 = SW128((wpix0 + nt * 8 + brow) * 128 + 64 + bcol);
            ldsm4(bx[nt], xtb + o0); ldsm4(bx[nt] + 4, xtb + o1);
        }
#pragma unroll
        for (int mt = 0; mt < 4; ++mt) {
            uint32_t aw[4][4];
            int ar = mt * 16 + (lane & 7) + ((lane >> 3) & 1) * 8;
#pragma unroll
            for (int kc = 0; kc < 4; ++kc)
                ldsm4(aw[kc], wtb + 16384 + SW128(ar * 128 + kc * 32 + acolb));
#pragma unroll
            for (int nt = 0; nt < 2; ++nt)
#pragma unroll
                for (int kc = 0; kc < 4; ++kc)
                    mma16816(chh[mt][nt], aw[kc], &bx[nt][kc * 2]);
        }
    }

    // epilogue
    int q = wpix0 + (lane >> 2);
    size_t fbase = (size_t)b * NPIX * HCH + (size_t)(n0 + q) * HCH;
    __half* fT = g_fT;
    __half* gT = g_gT;
#pragma unroll
    for (int nt = 0; nt < 8; ++nt) {
        int d = nt * 8 + (lane & 3) * 2;
        float b0 = bias_s[d], b1 = bias_s[d + 1];
        *(uint32_t*)&fT[fbase + d] =
            pack_h2(__float2half_rn(cf[nt][0] + b0), __float2half_rn(cf[nt][1] + b1));
        *(uint32_t*)&fT[fbase + 8 * HCH + d] =
            pack_h2(__float2half_rn(cf[nt][2] + b0), __float2half_rn(cf[nt][3] + b1));
        float c0g = bias_s[64 + d], c1g = bias_s[64 + d + 1];
        *(uint32_t*)&gT[fbase + d] =
            pack_h2(__float2half_rn(cg[nt][0] + c0g), __float2half_rn(cg[nt][1] + c1g));
        *(uint32_t*)&gT[fbase + 8 * HCH + d] =
            pack_h2(__float2half_rn(cg[nt][2] + c0g), __float2half_rn(cg[nt][3] + c1g));
    }
    __half* Hp = g_h + (size_t)b * HCH * NPIX;
#pragma unroll
    for (int mt = 0; mt < 4; ++mt) {
        int d0 = mt * 16 + (lane >> 2), d1 = d0 + 8;
        float bb0 = bias_s[128 + d0], bb1 = bias_s[128 + d1];
#pragma unroll
        for (int nt = 0; nt < 2; ++nt) {
            int pix = n0 + wpix0 + nt * 8 + (lane & 3) * 2;
            *(uint32_t*)&Hp[(size_t)d0 * NPIX + pix] =
                pack_h2(__float2half_rn(chh[mt][nt][0] + bb0), __float2half_rn(chh[mt][nt][1] + bb0));
            *(uint32_t*)&Hp[(size_t)d1 * NPIX + pix] =
                pack_h2(__float2half_rn(chh[mt][nt][2] + bb1), __float2half_rn(chh[mt][nt][3] + bb1));
        }
    }
}

// ---------------------------------------------------------------------------
// mma.sync (fp16) flash attention.  grid (32, B), 256 threads (8 warps x 16 q).
// ---------------------------------------------------------------------------
#define SM_FH 0
#define SM_BUF 16384
#define SM_ATTN_TOT 49152

__global__ void __launch_bounds__(256, 1) attn_kernel()
{
    extern __shared__ __align__(128) char smem[];
    int tid = threadIdx.x;
    int lane = tid & 31, wid = tid >> 5;
    int m0 = wid * 16;
    int b = blockIdx.y, n0 = blockIdx.x * 128;
    uint32_t sb = smem_u32(smem);

    size_t bo = (size_t)b * NPIX * HCH;
    const __half* fT = g_fT + bo + (size_t)n0 * HCH;
    const __half* gT = g_gT + bo;
    const __half* hp = g_h + (size_t)b * HCH * NPIX;

    cp_tile(sb + SM_FH, fT, 64, tid, 128);
    cp_tile(sb + SM_BUF,        gT, 64, tid, 64);
    cp_tile(sb + SM_BUF + 8192, hp, NPIX, tid, 64);
    CP_COMMIT();
    cp_tile(sb + SM_BUF + 16384, gT + 64 * 64, 64, tid, 64);
    cp_tile(sb + SM_BUF + 24576, hp + 64, NPIX, tid, 64);
    CP_COMMIT();

    CP_WAIT(1);
    __syncthreads();

    uint32_t fa[4][4];
    {
        int arow = m0 + (lane & 7) + ((lane >> 3) & 1) * 8;
        int acol = ((lane >> 4) & 1) * 16;
#pragma unroll
        for (int kc = 0; kc < 4; ++kc)
            ldsm4(fa[kc], sb + SM_FH + SW128(arow * 128 + kc * 32 + acol));
    }

    float oaccv[32];
#pragma unroll
    for (int i = 0; i < 32; ++i) oaccv[i] = 0.f;
    float m0r = -1e30f, m1r = -1e30f, l0 = 0.f, l1 = 0.f;

    int brow = lane & 7;
    int bj = lane >> 3;
    int bcol = (bj & 1) * 16 + (bj >> 1) * 32;

    for (int kt = 0; kt < 64; ++kt) {
        if (kt > 0) { CP_WAIT(1); __syncthreads(); }
        uint32_t gB = sb + SM_BUF + (kt & 1) * 16384;
        uint32_t hB = gB + 8192;

        float s[32];
#pragma unroll
        for (int i = 0; i < 32; ++i) s[i] = 0.f;
#pragma unroll
        for (int nt = 0; nt < 8; ++nt) {
            uint32_t bfr[8];
            uint32_t o0 = SW128((nt * 8 + brow) * 128 + 0 + bcol);
            uint32_t o1 = SW128((nt * 8 + brow) * 128 + 64 + bcol);
            ldsm4(bfr,     gB + o0);
            ldsm4(bfr + 4, gB + o1);
            float* s4 = &s[nt * 4];
#pragma unroll
            for (int kc = 0; kc < 4; ++kc) mma16816(s4, fa[kc], &bfr[kc * 2]);
        }

        float mx0 = -1e30f, mx1 = -1e30f;
#pragma unroll
        for (int nt = 0; nt < 8; ++nt) {
            mx0 = fmaxf(mx0, fmaxf(s[nt * 4 + 0], s[nt * 4 + 1]));
            mx1 = fmaxf(mx1, fmaxf(s[nt * 4 + 2], s[nt * 4 + 3]));
        }
        mx0 = fmaxf(mx0, __shfl_xor_sync(0xffffffffu, mx0, 1));
        mx0 = fmaxf(mx0, __shfl_xor_sync(0xffffffffu, mx0, 2));
        mx1 = fmaxf(mx1, __shfl_xor_sync(0xffffffffu, mx1, 1));
        mx1 = fmaxf(mx1, __shfl_xor_sync(0xffffffffu, mx1, 2));
        float mn0 = fmaxf(m0r, mx0), mn1 = fmaxf(m1r, mx1);
        float c0 = ex2(m0r - mn0), c1 = ex2(m1r - mn1);
        m0r = mn0; m1r = mn1;
        float ls0 = 0.f, ls1 = 0.f;
#pragma unroll
        for (int nt = 0; nt < 8; ++nt) {
            float p0 = ex2(s[nt * 4 + 0] - mn0);
            float p1 = ex2(s[nt * 4 + 1] - mn0);
            float p2 = ex2(s[nt * 4 + 2] - mn1);
            float p3 = ex2(s[nt * 4 + 3] - mn1);
            s[nt * 4 + 0] = p0; s[nt * 4 + 1] = p1;
            s[nt * 4 + 2] = p2; s[nt * 4 + 3] = p3;
            ls0 += p0 + p1; ls1 += p2 + p3;
        }
        l0 = l0 * c0 + ls0;
        l1 = l1 * c1 + ls1;
#pragma unroll
        for (int nt = 0; nt < 8; ++nt) {
            oaccv[nt * 4 + 0] *= c0; oaccv[nt * 4 + 1] *= c0;
            oaccv[nt * 4 + 2] *= c1; oaccv[nt * 4 + 3] *= c1;
        }

        uint32_t pa[4][4];
#pragma unroll
        for (int j = 0; j < 4; ++j) {
            float* sa = &s[(2 * j) * 4];
            float* sc = &s[(2 * j + 1) * 4];
            pa[j][0] = pack_h2(__float2half_rn(sa[0]), __float2half_rn(sa[1]));
            pa[j][1] = pack_h2(__float2half_rn(sa[2]), __float2half_rn(sa[3]));
            pa[j][2] = pack_h2(__float2half_rn(sc[0]), __float2half_rn(sc[1]));
            pa[j][3] = pack_h2(__float2half_rn(sc[2]), __float2half_rn(sc[3]));
        }

#pragma unroll
        for (int nd = 0; nd < 8; ++nd) {
            uint32_t bfr[8];
            uint32_t o0 = SW128((nd * 8 + brow) * 128 + 0 + bcol);
            uint32_t o1 = SW128((nd * 8 + brow) * 128 + 64 + bcol);
            ldsm4(bfr,     hB + o0);
            ldsm4(bfr + 4, hB + o1);
            float* o4 = &oaccv[nd * 4];
#pragma unroll
            for (int j = 0; j < 4; ++j) mma16816(o4, pa[j], &bfr[j * 2]);
        }

        __syncthreads();
        if (kt < 62) {
            uint32_t bb = sb + SM_BUF + (kt & 1) * 16384;
            cp_tile(bb,        gT + (size_t)(kt + 2) * 64 * 64, 64, tid, 64);
            cp_tile(bb + 8192, hp + (kt + 2) * 64, NPIX, tid, 64);
            CP_COMMIT();
        }
    }

    // epilogue: write o^T fp16 [pix][64] directly from fragments
    l0 += __shfl_xor_sync(0xffffffffu, l0, 1);
    l0 += __shfl_xor_sync(0xffffffffu, l0, 2);
    l1 += __shfl_xor_sync(0xffffffffu, l1, 1);
    l1 += __shfl_xor_sync(0xffffffffu, l1, 2);
    float inv0 = 1.f / l0, inv1 = 1.f / l1;

    int q0 = m0 + (lane >> 2), q1 = q0 + 8;
    size_t r0 = (size_t)b * NPIX * HCH + (size_t)(n0 + q0) * HCH;
    size_t r1 = (size_t)b * NPIX * HCH + (size_t)(n0 + q1) * HCH;
#pragma unroll
    for (int nt = 0; nt < 8; ++nt) {
        int d = nt * 8 + (lane & 3) * 2;
        *(uint32_t*)&g_oT[r0 + d] = pack_h2(__float2half_rn(oaccv[nt * 4 + 0] * inv0),
                                            __float2half_rn(oaccv[nt * 4 + 1] * inv0));
        *(uint32_t*)&g_oT[r1 + d] = pack_h2(__float2half_rn(oaccv[nt * 4 + 2] * inv1),
                                            __float2half_rn(oaccv[nt * 4 + 3] * inv1));
    }
}

// ---------------------------------------------------------------------------
// MMA outproj: out = gamma*(Wv' @ o + bv) + x.  grid (32, 8, 4), 256 threads.
// ---------------------------------------------------------------------------
__global__ void __launch_bounds__(256) outproj_kernel(
    const float* __restrict__ x, const float* __restrict__ bv,
    const float* __restrict__ gamma, float* __restrict__ out)
{
    __shared__ __align__(1024) char osm[24576];   // Wv tile 8KB @0, oT tile 16KB @8192
    int tid = threadIdx.x;
    int lane = tid & 31, wid = tid >> 5;
    int wpix0 = wid * 16;
    int nb = blockIdx.x, ct = blockIdx.y, b = blockIdx.z;
    int n0 = nb * 128, c0 = ct * 64;
    uint32_t sb = smem_u32(osm);

    cp_tile(sb, g_Wvp + c0 * 64, 64, tid, 64);
    cp_tile(sb + 8192, g_oT + ((size_t)b * NPIX + n0) * 64, 64, tid, 128);
    CP_COMMIT();
    CP_WAIT(0);
    __syncthreads();

    int brow = lane & 7;
    int bj = lane >> 3;
    int bcol = (bj & 1) * 16 + (bj >> 1) * 32;
    int acolb = ((lane >> 4) & 1) * 16;

    float co[4][2][4];
#pragma unroll
    for (int i = 0; i < 4; ++i)
#pragma unroll
        for (int n = 0; n < 2; ++n)
#pragma unroll
            for (int j = 0; j < 4; ++j) co[i][n][j] = 0.f;

    uint32_t bx[2][8];
#pragma unroll
    for (int nt = 0; nt < 2; ++nt) {
        uint32_t o0 = SW128((wpix0 + nt * 8 + brow) * 128 + bcol);
        uint32_t o1 = SW128((wpix0 + nt * 8 + brow) * 128 + 64 + bcol);
        ldsm4(bx[nt], sb + 8192 + o0); ldsm4(bx[nt] + 4, sb + 8192 + o1);
    }
#pragma unroll
    for (int mt = 0; mt < 4; ++mt) {
        uint32_t aw[4][4];
        int ar = mt * 16 + (lane & 7) + ((lane >> 3) & 1) * 8;
#pragma unroll
        for (int kc = 0; kc < 4; ++kc)
            ldsm4(aw[kc], sb + SW128(ar * 128 + kc * 32 + acolb));
#pragma unroll
        for (int nt = 0; nt < 2; ++nt)
#pragma unroll
            for (int kc = 0; kc < 4; ++kc)
                mma16816(co[mt][nt], aw[kc], &bx[nt][kc * 2]);
    }

    float gm = gamma[0];
#pragma unroll
    for (int mt = 0; mt < 4; ++mt) {
        int cA = c0 + mt * 16 + (lane >> 2);
        int cB = cA + 8;
        float bA = bv[cA], bB = bv[cB];
#pragma unroll
        for (int nt = 0; nt < 2; ++nt) {
            int pix = n0 + wpix0 + nt * 8 + (lane & 3) * 2;
            size_t iA = ((size_t)b * CCH + cA) * NPIX + pix;
            size_t iB = ((size_t)b * CCH + cB) * NPIX + pix;
            float2 xA = *(const float2*)&x[iA];
            float2 xB = *(const float2*)&x[iB];
            float2 oA, oB;
            oA.x = gm * (co[mt][nt][0] + bA) + xA.x;
            oA.y = gm * (co[mt][nt][1] + bA) + xA.y;
            oB.x = gm * (co[mt][nt][2] + bB) + xB.x;
            oB.y = gm * (co[mt][nt][3] + bB) + xB.y;
            *(float2*)&out[iA] = oA;
            *(float2*)&out[iB] = oB;
        }
    }
}

// ---------------------------------------------------------------------------
extern "C" void kernel_launch(void* const* d_in, const int* in_sizes, int n_in,
                              void* d_out, int out_size)
{
    const float* x     = (const float*)d_in[0];
    const float* Wf    = (const float*)d_in[1];
    const float* bf    = (const float*)d_in[2];
    const float* Wg    = (const float*)d_in[3];
    const float* bg    = (const float*)d_in[4];
    const float* Wh    = (const float*)d_in[5];
    const float* bh    = (const float*)d_in[6];
    const float* Wv    = (const float*)d_in[7];
    const float* bv    = (const float*)d_in[8];
    const float* uf    = (const float*)d_in[9];
    const float* ug    = (const float*)d_in[10];
    const float* uh    = (const float*)d_in[11];
    const float* uv    = (const float*)d_in[12];
    const float* gamma = (const float*)d_in[13];
    float* out = (float*)d_out;

    cudaFuncSetAttribute(attn_kernel, cudaFuncAttributeMaxDynamicSharedMemorySize, SM_ATTN_TOT);
    cudaFuncSetAttribute(proj_kernel, cudaFuncAttributeMaxDynamicSharedMemorySize, SM_PROJ_TOT);

    spectral_kernel<<<4, 512>>>(Wf, Wg, Wh, Wv, uf, ug, uh, uv);
    wconv_kernel<<<128, 256>>>(Wf, Wg, Wh, Wv);
    proj_kernel<<<dim3(NPIX / 128, BATCH), 256, SM_PROJ_TOT>>>(x, bf, bg, bh);
    attn_kernel<<<dim3(NPIX / 128, BATCH), 256, SM_ATTN_TOT>>>();
    outproj_kernel<<<dim3(NPIX / 128, CCH / 64, BATCH), 256>>>(x, bv, gamma, out);
}